// round 16
// baseline (speedup 1.0000x reference)
#include <cuda_runtime.h>
#include <cuda_fp16.h>
#include <math.h>
#include <stdint.h>

// ---------------- problem constants ----------------
#define B_TOTAL   131072
#define DH        32
#define TWO_PI_F  6.283185307179586f

// ---------------- device scratch (static, no alloc) ----------------
__device__ __half g_xhi[(size_t)B_TOTAL * 64];
__device__ __half g_xlo[(size_t)B_TOTAL * 64];
__device__ __half g_hhi[(size_t)B_TOTAL * 512];
__device__ __half g_hlo[(size_t)B_TOTAL * 512];
__device__ __half g_w1hi[512 * 64];    // W1^T [n=512][k=64]
__device__ __half g_w1lo[512 * 64];
__device__ __half g_w2hi[512 * 512];   // (W2*eta)^T [n=512][k=512]
__device__ __half g_w2lo[512 * 512];

__device__ __forceinline__ void split_h(float v, __half& hi, __half& lo) {
    hi = __float2half_rn(v);
    lo = __float2half_rn(v - __half2float(hi));
}

// ---------------- combined pack kernel (x4 vectorized) ----------------
__global__ void pack_all_kernel(const float* __restrict__ x,
                                const float* __restrict__ W1,
                                const float* __restrict__ W2,
                                const float* __restrict__ eta) {
    int bid = blockIdx.x, tid = threadIdx.x;
    if (bid < 8192) {                        // x: B*64 elems, 4 per thread
        size_t i4 = ((size_t)bid * 256 + tid) * 4;
        float4 v = *reinterpret_cast<const float4*>(x + i4);
        __half h0, l0, h1, l1, h2, l2, h3, l3;
        split_h(v.x, h0, l0);
        split_h(v.y, h1, l1);
        split_h(v.z, h2, l2);
        split_h(v.w, h3, l3);
        *reinterpret_cast<__half2*>(&g_xhi[i4])     = __halves2half2(h0, h1);
        *reinterpret_cast<__half2*>(&g_xhi[i4 + 2]) = __halves2half2(h2, h3);
        *reinterpret_cast<__half2*>(&g_xlo[i4])     = __halves2half2(l0, l1);
        *reinterpret_cast<__half2*>(&g_xlo[i4 + 2]) = __halves2half2(l2, l3);
    } else if (bid < 8192 + 32) {            // W1^T: 512*64, 4 k per thread
        int q = ((bid - 8192) * 256 + tid) * 4;
        int n = q >> 6, k = q & 63;
#pragma unroll
        for (int j = 0; j < 4; j++) {
            __half hi, lo;
            split_h(W1[(k + j) * 512 + n], hi, lo);
            g_w1hi[n * 64 + k + j] = hi;
            g_w1lo[n * 64 + k + j] = lo;
        }
    } else {                                 // W2^T*eta: 512*512, 4 k per thread
        int q = ((bid - 8224) * 256 + tid) * 4;
        int n = q >> 9, k = q & 511;
        float e = eta[0];
#pragma unroll
        for (int j = 0; j < 4; j++) {
            __half hi, lo;
            split_h(W2[(k + j) * 513 + n] * e, hi, lo);
            g_w2hi[n * 512 + k + j] = hi;
            g_w2lo[n * 512 + k + j] = lo;
        }
    }
}

#define LDSM_X4(r0, r1, r2, r3, addr)                                        \
    asm volatile(                                                            \
        "ldmatrix.sync.aligned.m8n8.x4.shared.b16 {%0,%1,%2,%3}, [%4];"      \
        : "=r"(r0), "=r"(r1), "=r"(r2), "=r"(r3) : "r"(addr))

#define MMA16816(d, a, b)                                                    \
    asm volatile(                                                            \
        "mma.sync.aligned.m16n8k16.row.col.f32.f16.f16.f32 "                 \
        "{%0,%1,%2,%3}, {%4,%5,%6,%7}, {%8,%9}, {%0,%1,%2,%3};"              \
        : "+f"((d)[0]), "+f"((d)[1]), "+f"((d)[2]), "+f"((d)[3])             \
        : "r"((a)[0]), "r"((a)[1]), "r"((a)[2]), "r"((a)[3]),                \
          "r"((b)[0]), "r"((b)[1]))

// shared thread-mapping for the N=64 / 3-CTA kernels (warp tile 32x32)
#define SETUP_N64()                                                          \
    const int tid = threadIdx.x;                                             \
    const int lane = tid & 31;                                               \
    const int wid = tid >> 5;                                                \
    const int wm = (wid & 3) * 32;                                           \
    const int wn = (wid >> 2) * 32;                                          \
    const int aRow = wm + (lane & 7) + ((lane >> 3) & 1) * 8;                \
    const int aU = (lane >> 4) & 1;                                          \
    const int aX = aRow & 7;                                                 \
    const int bRow = wn + (lane & 7) + ((lane >> 4) & 1) * 8;                \
    const int bU = (lane >> 3) & 1;                                          \
    const int bX = bRow & 7;                                                 \
    const int g = lane >> 2;                                                 \
    const int tig = lane & 3;                                                \
    float acc[2][4][4];                                                      \
    _Pragma("unroll")                                                        \
    for (int mi = 0; mi < 2; mi++)                                           \
        _Pragma("unroll")                                                    \
        for (int nj = 0; nj < 4; nj++)                                       \
            _Pragma("unroll")                                                \
            for (int q = 0; q < 4; q++) acc[mi][nj][q] = 0.0f;

// chunk load for N=64 tiles: A 128rows(16KB) + B 64rows(8KB), 24KB/chunk
#define LOADC64(AH, AL, BH, BL, SSTR, blockRow, colbase, kc, buf)            \
    do {                                                                     \
        const char* ah_ = (const char*)(AH) + (size_t)(blockRow) * (SSTR) +  \
                          (size_t)(kc) * 64;                                 \
        const char* al_ = (const char*)(AL) + (size_t)(blockRow) * (SSTR) +  \
                          (size_t)(kc) * 64;                                 \
        const char* bh_ = (const char*)(BH) + (size_t)(colbase) * (SSTR) +   \
                          (size_t)(kc) * 64;                                 \
        const char* bl_ = (const char*)(BL) + (size_t)(colbase) * (SSTR) +   \
                          (size_t)(kc) * 64;                                 \
        uint32_t ab_ = sbase + (uint32_t)(buf) * 24576u;                     \
        uint32_t bb_ = ab_ + 16384u;                                         \
        _Pragma("unroll")                                                    \
        for (int j_ = 0; j_ < 4; j_++) {                                     \
            int gi_ = tid + 256 * j_;                                        \
            int row_ = gi_ >> 3, u_ = gi_ & 7;                               \
            const char* src_ = ((u_ < 4) ? ah_ : al_) +                      \
                               (size_t)row_ * (SSTR) + (u_ & 3) * 16;        \
            uint32_t dst_ = ab_ + row_ * 128u +                              \
                            (uint32_t)((u_ ^ (row_ & 7)) << 4);              \
            asm volatile("cp.async.cg.shared.global [%0], [%1], 16;"         \
                         :: "r"(dst_), "l"(src_));                           \
        }                                                                    \
        _Pragma("unroll")                                                    \
        for (int j_ = 0; j_ < 2; j_++) {                                     \
            int gi_ = tid + 256 * j_;                                        \
            int row_ = gi_ >> 3, u_ = gi_ & 7;                               \
            const char* src_ = ((u_ < 4) ? bh_ : bl_) +                      \
                               (size_t)row_ * (SSTR) + (u_ & 3) * 16;        \
            uint32_t dst_ = bb_ + row_ * 128u +                              \
                            (uint32_t)((u_ ^ (row_ & 7)) << 4);              \
            asm volatile("cp.async.cg.shared.global [%0], [%1], 16;"         \
                         :: "r"(dst_), "l"(src_));                           \
        }                                                                    \
        asm volatile("cp.async.commit_group;");                              \
    } while (0)

// one k32 fused-chunk compute for N=64: 3 products x 2 k16 steps
#define CHUNK_MMA64(buf)                                                     \
    do {                                                                     \
        uint32_t ab_ = sbase + (uint32_t)(buf) * 24576u;                     \
        uint32_t bb_ = ab_ + 16384u;                                         \
        _Pragma("unroll")                                                    \
        for (int kk = 0; kk < 2; kk++) {                                     \
            uint32_t a_hi[2][4], a_lo[2][4], b[4][2];                        \
            _Pragma("unroll")                                                \
            for (int mi = 0; mi < 2; mi++) {                                 \
                int row = aRow + mi * 16;                                    \
                uint32_t ad = ab_ + row * 128u +                             \
                              (uint32_t)(((kk * 2 + aU) ^ aX) << 4);         \
                LDSM_X4(a_hi[mi][0], a_hi[mi][1], a_hi[mi][2], a_hi[mi][3],  \
                        ad);                                                 \
            }                                                                \
            _Pragma("unroll")                                                \
            for (int p = 0; p < 2; p++) {                                    \
                int row = bRow + p * 16;                                     \
                uint32_t bd = bb_ + row * 128u +                             \
                              (uint32_t)(((kk * 2 + bU) ^ bX) << 4);         \
                LDSM_X4(b[2 * p][0], b[2 * p][1],                            \
                        b[2 * p + 1][0], b[2 * p + 1][1], bd);               \
            }                                                                \
            _Pragma("unroll")                                                \
            for (int mi = 0; mi < 2; mi++) {                                 \
                int row = aRow + mi * 16;                                    \
                uint32_t ad = ab_ + row * 128u +                             \
                              (uint32_t)(((4 + kk * 2 + aU) ^ aX) << 4);     \
                LDSM_X4(a_lo[mi][0], a_lo[mi][1], a_lo[mi][2], a_lo[mi][3],  \
                        ad);                                                 \
            }                                                                \
            _Pragma("unroll")                                                \
            for (int mi = 0; mi < 2; mi++)                                   \
                _Pragma("unroll")                                            \
                for (int nj = 0; nj < 4; nj++)                               \
                    MMA16816(acc[mi][nj], a_hi[mi], b[nj]);                  \
            _Pragma("unroll")                                                \
            for (int mi = 0; mi < 2; mi++)                                   \
                _Pragma("unroll")                                            \
                for (int nj = 0; nj < 4; nj++)                               \
                    MMA16816(acc[mi][nj], a_lo[mi], b[nj]);                  \
            _Pragma("unroll")                                                \
            for (int p = 0; p < 2; p++) {                                    \
                int row = bRow + p * 16;                                     \
                uint32_t bd = bb_ + row * 128u +                             \
                              (uint32_t)(((4 + kk * 2 + bU) ^ bX) << 4);     \
                LDSM_X4(b[2 * p][0], b[2 * p][1],                            \
                        b[2 * p + 1][0], b[2 * p + 1][1], bd);               \
            }                                                                \
            _Pragma("unroll")                                                \
            for (int mi = 0; mi < 2; mi++)                                   \
                _Pragma("unroll")                                            \
                for (int nj = 0; nj < 4; nj++)                               \
                    MMA16816(acc[mi][nj], a_hi[mi], b[nj]);                  \
        }                                                                    \
    } while (0)

// ===================== PHASE 1: N=64 tile, 3 CTAs/SM ========================
// h = relu(x@W1+b1) + fp16 split. NC=2 k32 chunks, 2 stages (48KB/CTA).
// Grid (8, 1024) x-fast: 8 row-sharing CTAs adjacent -> x reads L2-hot.
__global__ __launch_bounds__(256, 3)
void mma_phase1_kernel(const float* __restrict__ b1) {
    extern __shared__ char smem[];
    const uint32_t sbase = (uint32_t)__cvta_generic_to_shared(smem);
    SETUP_N64();
    const int blockRow = blockIdx.y * 128;
    const int colbase = blockIdx.x * 64;
    constexpr int SSTR = 128;    // 64 halves * 2B

    LOADC64(g_xhi, g_xlo, g_w1hi, g_w1lo, SSTR, blockRow, colbase, 0, 0);
    LOADC64(g_xhi, g_xlo, g_w1hi, g_w1lo, SSTR, blockRow, colbase, 1, 1);
    asm volatile("cp.async.wait_group 1;");
    __syncthreads();
    CHUNK_MMA64(0);
    asm volatile("cp.async.wait_group 0;");
    __syncthreads();
    CHUNK_MMA64(1);

    // epilogue: relu + split, staged in smem (stride 72 halves), coalesced out
    __half* s_hi = reinterpret_cast<__half*>(smem);              // 128x72
    __half* s_lo = reinterpret_cast<__half*>(smem + 128 * 144);  // 128x72
    __syncthreads();   // all LDSM reads of chunk smem done before overwrite
#pragma unroll
    for (int mi = 0; mi < 2; mi++)
#pragma unroll
        for (int rsel = 0; rsel < 2; rsel++) {
            int rloc = wm + mi * 16 + g + rsel * 8;
#pragma unroll
            for (int nj = 0; nj < 4; nj++) {
                int cloc = wn + nj * 8 + 2 * tig;
                int cc = colbase + cloc;
                float h0 = fmaxf(acc[mi][nj][rsel * 2 + 0] + b1[cc], 0.0f);
                float h1 = fmaxf(acc[mi][nj][rsel * 2 + 1] + b1[cc + 1], 0.0f);
                __half hi0, lo0, hi1, lo1;
                split_h(h0, hi0, lo0);
                split_h(h1, hi1, lo1);
                *reinterpret_cast<__half2*>(&s_hi[rloc * 72 + cloc]) =
                    __halves2half2(hi0, hi1);
                *reinterpret_cast<__half2*>(&s_lo[rloc * 72 + cloc]) =
                    __halves2half2(lo0, lo1);
            }
        }
    __syncthreads();
#pragma unroll
    for (int it = 0; it < 4; it++) {
        int idx = tid + it * 256;            // 1024 = 128 rows x 8 segs
        int row = idx >> 3, seg = idx & 7;
        uint4 v = *reinterpret_cast<uint4*>(&s_hi[row * 72 + seg * 8]);
        *reinterpret_cast<uint4*>(
            &g_hhi[(size_t)(blockRow + row) * 512 + colbase + seg * 8]) = v;
        uint4 w = *reinterpret_cast<uint4*>(&s_lo[row * 72 + seg * 8]);
        *reinterpret_cast<uint4*>(
            &g_hlo[(size_t)(blockRow + row) * 512 + colbase + seg * 8]) = w;
    }
}

// ===================== PHASE 2: N=64 tile, 3 CTAs/SM (unchanged core) ======
// params = h@(W2*eta) + Moebius. NC=16 k32 chunks, 3 stages (72KB/CTA).
// L2-prefetch of theta/r/b2 at entry so epilogue LDGs hit L2, not DRAM.
__global__ __launch_bounds__(256, 3)
void mma_phase2_kernel(const float* __restrict__ b2,
                       const float* __restrict__ theta,
                       const float* __restrict__ r_in,
                       const float* __restrict__ eta,
                       float* __restrict__ out) {
    extern __shared__ char smem[];
    const uint32_t sbase = (uint32_t)__cvta_generic_to_shared(smem);
    SETUP_N64();
    const int blockRow = blockIdx.y * 128;
    const int colbase = blockIdx.x * 64;
    constexpr int SSTR = 1024;
    constexpr int NC = 16;

    // warm L2 for the epilogue's scattered operands (no registers consumed)
    if (tid < 128) {
        const char* pt = (const char*)theta + (size_t)(blockRow + tid) * 128 +
                         blockIdx.x * 16;
        const char* pr = (const char*)r_in + (size_t)(blockRow + tid) * 128 +
                         blockIdx.x * 16;
        asm volatile("prefetch.global.L2 [%0];" :: "l"(pt));
        asm volatile("prefetch.global.L2 [%0];" :: "l"(pr));
        if (tid == 0)
            asm volatile("prefetch.global.L2 [%0];"
                         :: "l"((const char*)b2 + colbase * 4));
    }

    LOADC64(g_hhi, g_hlo, g_w2hi, g_w2lo, SSTR, blockRow, colbase, 0, 0);
    LOADC64(g_hhi, g_hlo, g_w2hi, g_w2lo, SSTR, blockRow, colbase, 1, 1);
    asm volatile("cp.async.wait_group 1;");
    __syncthreads();

#pragma unroll 1
    for (int c = 0; c < NC; c++) {
        if (c + 2 < NC) {
            int kc = c + 2;
            LOADC64(g_hhi, g_hlo, g_w2hi, g_w2lo, SSTR, blockRow, colbase,
                    kc, kc % 3);
        } else {
            asm volatile("cp.async.commit_group;");
        }
        CHUNK_MMA64(c % 3);
        asm volatile("cp.async.wait_group 1;");
        __syncthreads();
    }

    // ---- Moebius epilogue ----
    const float e = eta[0];
    float bb2[4][2];
#pragma unroll
    for (int nj = 0; nj < 4; nj++) {
        int cc = colbase + wn + nj * 8 + 2 * tig;
        bb2[nj][0] = b2[cc] * e;
        bb2[nj][1] = b2[cc + 1] * e;
    }
    const int d0c = colbase >> 4;           // blockIdx.x * 4
    const int dbloc = wn >> 4;              // 0 or 2
    float* s_out = reinterpret_cast<float*>(smem);   // 128 x 9 floats

#pragma unroll
    for (int mi = 0; mi < 2; mi++)
#pragma unroll
        for (int rsel = 0; rsel < 2; rsel++) {
            int rloc = wm + mi * 16 + g + rsel * 8;
            int grow = blockRow + rloc;
#pragma unroll
            for (int dj = 0; dj < 2; dj++) {
                int dl = dbloc + dj;        // 0..3 within CTA
                int d = d0c + dl;
                float th = theta[grow * DH + d];
                float rr = r_in[grow * DH + d];
                float sn, cs;
                sincosf(th, &sn, &cs);
                float z0 = rr * cs, z1 = rr * sn;
                float rr2 = rr * rr;
                float sumT = 0.0f, sumS = 0.0f;
#pragma unroll
                for (int hf = 0; hf < 2; hf++) {
                    int nj = 2 * dj + hf;
                    float p0 = acc[mi][nj][rsel * 2 + 0] + bb2[nj][0];
                    float p1 = acc[mi][nj][rsel * 2 + 1] + bb2[nj][1];
                    float nrm = sqrtf(p0 * p0 + p1 * p1);
                    float f = rr * 0.99f / (1.0f + nrm);
                    float w0 = f * p0, w1 = f * p1;
                    float zw0 = z0 - w0, zw1 = z1 - w1;
                    float dist2 = zw0 * zw0 + zw1 * zw1;
                    float scale = (rr2 - (w0 * w0 + w1 * w1)) / dist2;
                    float zo0 = scale * zw0 - w0;
                    float zo1 = scale * zw1 - w1;
                    float ang = atan2f(zo1, zo0);
                    if (ang < 0.0f) ang += TWO_PI_F;
                    sumT += ang;
                    sumS += scale;
                }
                sumT += __shfl_xor_sync(0xffffffffu, sumT, 1);
                sumS += __shfl_xor_sync(0xffffffffu, sumS, 1);
                sumT += __shfl_xor_sync(0xffffffffu, sumT, 2);
                sumS += __shfl_xor_sync(0xffffffffu, sumS, 2);
                if (tig == 0) {
                    s_out[rloc * 9 + dl] = sumT * 0.125f;
                    s_out[rloc * 9 + 4 + dl] = logf(sumS * 0.125f + 1e-8f);
                }
            }
        }
    __syncthreads();
#pragma unroll
    for (int it = 0; it < 4; it++) {
        int idx = tid + it * 256;           // 1024 = 128 rows x 2 tensors x 4 d
        int row = idx >> 3;
        int rest = idx & 7;
        int t = rest >> 2;
        int dl = rest & 3;
        float v = s_out[row * 9 + t * 4 + dl];
        out[(size_t)t * B_TOTAL * DH + (size_t)(blockRow + row) * DH +
            d0c + dl] = v;
    }
}

// ---------------- launch ----------------
extern "C" void kernel_launch(void* const* d_in, const int* in_sizes, int n_in,
                              void* d_out, int out_size) {
    const float* theta = (const float*)d_in[0];
    const float* r     = (const float*)d_in[1];
    const float* x     = (const float*)d_in[2];
    const float* W1    = (const float*)d_in[3];
    const float* b1    = (const float*)d_in[4];
    const float* W2    = (const float*)d_in[5];
    const float* b2    = (const float*)d_in[6];
    const float* eta   = (const float*)d_in[7];
    float* out = (float*)d_out;

    pack_all_kernel<<<8192 + 32 + 256, 256>>>(x, W1, W2, eta);

    const int smem1 = 2 * 24576;         // 48 KB, 2 stages, 3 CTAs/SM
    const int smem2 = 3 * 24576;         // 72 KB, 3 stages, 3 CTAs/SM
    cudaFuncSetAttribute(mma_phase1_kernel,
                         cudaFuncAttributeMaxDynamicSharedMemorySize, smem1);
    cudaFuncSetAttribute(mma_phase2_kernel,
                         cudaFuncAttributeMaxDynamicSharedMemorySize, smem2);

    dim3 grid(8, B_TOTAL / 128);
    mma_phase1_kernel<<<grid, 256, smem1>>>(b1);
    mma_phase2_kernel<<<grid, 256, smem2>>>(b2, theta, r, eta, out);
}

// round 17
// speedup vs baseline: 1.0795x; 1.0795x over previous
#include <cuda_runtime.h>
#include <cuda_fp16.h>
#include <math.h>
#include <stdint.h>

// ---------------- problem constants ----------------
#define B_TOTAL   131072
#define DH        32
#define TWO_PI_F  6.283185307179586f

// ---------------- device scratch (static, no alloc) ----------------
__device__ __half g_xhi[(size_t)B_TOTAL * 64];
__device__ __half g_xlo[(size_t)B_TOTAL * 64];
__device__ __half g_hhi[(size_t)B_TOTAL * 512];
__device__ __half g_hlo[(size_t)B_TOTAL * 512];
__device__ __half g_w1hi[512 * 64];    // W1^T [n=512][k=64]
__device__ __half g_w1lo[512 * 64];
__device__ __half g_w2hi[512 * 512];   // (W2*eta)^T [n=512][k=512]
__device__ __half g_w2lo[512 * 512];

__device__ __forceinline__ void split_h(float v, __half& hi, __half& lo) {
    hi = __float2half_rn(v);
    lo = __float2half_rn(v - __half2float(hi));
}

// ---------------- combined pack kernel (x4 vectorized) ----------------
__global__ void pack_all_kernel(const float* __restrict__ x,
                                const float* __restrict__ W1,
                                const float* __restrict__ W2,
                                const float* __restrict__ eta) {
    int bid = blockIdx.x, tid = threadIdx.x;
    if (bid < 8192) {                        // x: B*64 elems, 4 per thread
        size_t i4 = ((size_t)bid * 256 + tid) * 4;
        float4 v = *reinterpret_cast<const float4*>(x + i4);
        __half h0, l0, h1, l1, h2, l2, h3, l3;
        split_h(v.x, h0, l0);
        split_h(v.y, h1, l1);
        split_h(v.z, h2, l2);
        split_h(v.w, h3, l3);
        *reinterpret_cast<__half2*>(&g_xhi[i4])     = __halves2half2(h0, h1);
        *reinterpret_cast<__half2*>(&g_xhi[i4 + 2]) = __halves2half2(h2, h3);
        *reinterpret_cast<__half2*>(&g_xlo[i4])     = __halves2half2(l0, l1);
        *reinterpret_cast<__half2*>(&g_xlo[i4 + 2]) = __halves2half2(l2, l3);
    } else if (bid < 8192 + 32) {            // W1^T: 512*64, 4 k per thread
        int q = ((bid - 8192) * 256 + tid) * 4;
        int n = q >> 6, k = q & 63;
#pragma unroll
        for (int j = 0; j < 4; j++) {
            __half hi, lo;
            split_h(W1[(k + j) * 512 + n], hi, lo);
            g_w1hi[n * 64 + k + j] = hi;
            g_w1lo[n * 64 + k + j] = lo;
        }
    } else {                                 // W2^T*eta: 512*512, 4 k per thread
        int q = ((bid - 8224) * 256 + tid) * 4;
        int n = q >> 9, k = q & 511;
        float e = eta[0];
#pragma unroll
        for (int j = 0; j < 4; j++) {
            __half hi, lo;
            split_h(W2[(k + j) * 513 + n] * e, hi, lo);
            g_w2hi[n * 512 + k + j] = hi;
            g_w2lo[n * 512 + k + j] = lo;
        }
    }
}

#define LDSM_X4(r0, r1, r2, r3, addr)                                        \
    asm volatile(                                                            \
        "ldmatrix.sync.aligned.m8n8.x4.shared.b16 {%0,%1,%2,%3}, [%4];"      \
        : "=r"(r0), "=r"(r1), "=r"(r2), "=r"(r3) : "r"(addr))

#define MMA16816(d, a, b)                                                    \
    asm volatile(                                                            \
        "mma.sync.aligned.m16n8k16.row.col.f32.f16.f16.f32 "                 \
        "{%0,%1,%2,%3}, {%4,%5,%6,%7}, {%8,%9}, {%0,%1,%2,%3};"              \
        : "+f"((d)[0]), "+f"((d)[1]), "+f"((d)[2]), "+f"((d)[3])             \
        : "r"((a)[0]), "r"((a)[1]), "r"((a)[2]), "r"((a)[3]),                \
          "r"((b)[0]), "r"((b)[1]))

// =========================== PHASE 1 ======================================
// h = relu(x@W1+b1) + fp16 split. Grid (4 col-tiles, 256 row-pairs),
// 256 thr, 2 CTAs/SM, tile M128 x N128, warp 32x64 (acc[2][8][4]).
// W1 tile (2 x 16KB) loaded ONCE and kept resident; 2 row-tiles of A are
// processed per CTA with next-tile A loads overlapped under compute/epilogue.
// smem: B0 B1 A0 A1 (64KB) + 34KB hi/lo staging = 98KB.

// load one 128-row x 128B fused hi/lo tile (SSTR=128B source rows)
#define LOADT16(HI, LO, rowoff, kc, dstaddr)                                 \
    do {                                                                     \
        const char* h_ = (const char*)(HI) + (size_t)(rowoff) * 128 +        \
                         (size_t)(kc) * 64;                                  \
        const char* l_ = (const char*)(LO) + (size_t)(rowoff) * 128 +        \
                         (size_t)(kc) * 64;                                  \
        _Pragma("unroll")                                                    \
        for (int j_ = 0; j_ < 4; j_++) {                                     \
            int gi_ = tid + 256 * j_;                                        \
            int row_ = gi_ >> 3, u_ = gi_ & 7;                               \
            const char* src_ = ((u_ < 4) ? h_ : l_) +                        \
                               (size_t)row_ * 128 + (u_ & 3) * 16;           \
            uint32_t dst_ = (dstaddr) + row_ * 128u +                        \
                            (uint32_t)((u_ ^ (row_ & 7)) << 4);              \
            asm volatile("cp.async.cg.shared.global [%0], [%1], 16;"         \
                         :: "r"(dst_), "l"(src_));                           \
        }                                                                    \
        asm volatile("cp.async.commit_group;");                              \
    } while (0)

// one k32 fused-chunk compute, N=128 warp tile 32x64 (A buf, B buf explicit)
#define CHUNKP(abuf, bbuf)                                                   \
    do {                                                                     \
        uint32_t ab_ = (abuf), bb_ = (bbuf);                                 \
        _Pragma("unroll")                                                    \
        for (int kk = 0; kk < 2; kk++) {                                     \
            uint32_t a_hi[2][4], a_lo[2][4];                                 \
            uint32_t b_hi[8][2], b_lo[8][2];                                 \
            _Pragma("unroll")                                                \
            for (int mi = 0; mi < 2; mi++) {                                 \
                int row = aRow + mi * 16;                                    \
                uint32_t ad = ab_ + row * 128u +                             \
                              (uint32_t)(((kk * 2 + aU) ^ aX) << 4);         \
                LDSM_X4(a_hi[mi][0], a_hi[mi][1], a_hi[mi][2], a_hi[mi][3],  \
                        ad);                                                 \
            }                                                                \
            _Pragma("unroll")                                                \
            for (int p = 0; p < 4; p++) {                                    \
                int row = bRow + p * 16;                                     \
                uint32_t bd = bb_ + row * 128u +                             \
                              (uint32_t)(((kk * 2 + bU) ^ bX) << 4);         \
                LDSM_X4(b_hi[2 * p][0], b_hi[2 * p][1],                      \
                        b_hi[2 * p + 1][0], b_hi[2 * p + 1][1], bd);         \
            }                                                                \
            _Pragma("unroll")                                                \
            for (int mi = 0; mi < 2; mi++) {                                 \
                int row = aRow + mi * 16;                                    \
                uint32_t ad = ab_ + row * 128u +                             \
                              (uint32_t)(((4 + kk * 2 + aU) ^ aX) << 4);     \
                LDSM_X4(a_lo[mi][0], a_lo[mi][1], a_lo[mi][2], a_lo[mi][3],  \
                        ad);                                                 \
            }                                                                \
            _Pragma("unroll")                                                \
            for (int mi = 0; mi < 2; mi++)                                   \
                _Pragma("unroll")                                            \
                for (int nj = 0; nj < 8; nj++)                               \
                    MMA16816(acc[mi][nj], a_hi[mi], b_hi[nj]);               \
            _Pragma("unroll")                                                \
            for (int p = 0; p < 4; p++) {                                    \
                int row = bRow + p * 16;                                     \
                uint32_t bd = bb_ + row * 128u +                             \
                              (uint32_t)(((4 + kk * 2 + bU) ^ bX) << 4);     \
                LDSM_X4(b_lo[2 * p][0], b_lo[2 * p][1],                      \
                        b_lo[2 * p + 1][0], b_lo[2 * p + 1][1], bd);         \
            }                                                                \
            _Pragma("unroll")                                                \
            for (int mi = 0; mi < 2; mi++)                                   \
                _Pragma("unroll")                                            \
                for (int nj = 0; nj < 8; nj++)                               \
                    MMA16816(acc[mi][nj], a_lo[mi], b_hi[nj]);               \
            _Pragma("unroll")                                                \
            for (int mi = 0; mi < 2; mi++)                                   \
                _Pragma("unroll")                                            \
                for (int nj = 0; nj < 8; nj++)                               \
                    MMA16816(acc[mi][nj], a_hi[mi], b_lo[nj]);               \
        }                                                                    \
    } while (0)

// two-pass (hi then lo) epilogue through one 128x136-half staging buffer;
// per-element math identical to the one-pass version. Zeroes acc at the end.
#define EPI1(br)                                                             \
    do {                                                                     \
        __half* s_st = reinterpret_cast<__half*>(smem + 65536);              \
        _Pragma("unroll")                                                    \
        for (int mi = 0; mi < 2; mi++)                                       \
            _Pragma("unroll")                                                \
            for (int rsel = 0; rsel < 2; rsel++) {                           \
                int rloc = wm + mi * 16 + g + rsel * 8;                      \
                _Pragma("unroll")                                            \
                for (int nj = 0; nj < 8; nj++) {                             \
                    int cloc = wn + nj * 8 + 2 * tig;                        \
                    int cc = colbase + cloc;                                 \
                    float h0 = fmaxf(acc[mi][nj][rsel * 2 + 0] + b1[cc],     \
                                     0.0f);                                  \
                    float h1 = fmaxf(acc[mi][nj][rsel * 2 + 1] + b1[cc + 1], \
                                     0.0f);                                  \
                    *reinterpret_cast<__half2*>(&s_st[rloc * 136 + cloc]) =  \
                        __halves2half2(__float2half_rn(h0),                  \
                                       __float2half_rn(h1));                 \
                }                                                            \
            }                                                                \
        __syncthreads();                                                     \
        _Pragma("unroll")                                                    \
        for (int it = 0; it < 8; it++) {                                     \
            int idx = tid + it * 256;                                        \
            int row = idx >> 4, seg = idx & 15;                              \
            uint4 v = *reinterpret_cast<uint4*>(&s_st[row * 136 + seg * 8]); \
            *reinterpret_cast<uint4*>(                                       \
                &g_hhi[(size_t)((br) + row) * 512 + colbase + seg * 8]) = v; \
        }                                                                    \
        __syncthreads();                                                     \
        _Pragma("unroll")                                                    \
        for (int mi = 0; mi < 2; mi++)                                       \
            _Pragma("unroll")                                                \
            for (int rsel = 0; rsel < 2; rsel++) {                           \
                int rloc = wm + mi * 16 + g + rsel * 8;                      \
                _Pragma("unroll")                                            \
                for (int nj = 0; nj < 8; nj++) {                             \
                    int cloc = wn + nj * 8 + 2 * tig;                        \
                    int cc = colbase + cloc;                                 \
                    float h0 = fmaxf(acc[mi][nj][rsel * 2 + 0] + b1[cc],     \
                                     0.0f);                                  \
                    float h1 = fmaxf(acc[mi][nj][rsel * 2 + 1] + b1[cc + 1], \
                                     0.0f);                                  \
                    __half hi0 = __float2half_rn(h0);                        \
                    __half hi1 = __float2half_rn(h1);                        \
                    __half lo0 = __float2half_rn(h0 - __half2float(hi0));    \
                    __half lo1 = __float2half_rn(h1 - __half2float(hi1));    \
                    *reinterpret_cast<__half2*>(&s_st[rloc * 136 + cloc]) =  \
                        __halves2half2(lo0, lo1);                            \
                }                                                            \
            }                                                                \
        __syncthreads();                                                     \
        _Pragma("unroll")                                                    \
        for (int it = 0; it < 8; it++) {                                     \
            int idx = tid + it * 256;                                        \
            int row = idx >> 4, seg = idx & 15;                              \
            uint4 v = *reinterpret_cast<uint4*>(&s_st[row * 136 + seg * 8]); \
            *reinterpret_cast<uint4*>(                                       \
                &g_hlo[(size_t)((br) + row) * 512 + colbase + seg * 8]) = v; \
        }                                                                    \
        __syncthreads();                                                     \
        _Pragma("unroll")                                                    \
        for (int mi = 0; mi < 2; mi++)                                       \
            _Pragma("unroll")                                                \
            for (int nj = 0; nj < 8; nj++)                                   \
                _Pragma("unroll")                                            \
                for (int q = 0; q < 4; q++) acc[mi][nj][q] = 0.0f;           \
    } while (0)

__global__ __launch_bounds__(256, 2)
void mma_phase1_kernel(const float* __restrict__ b1) {
    extern __shared__ char smem[];
    const uint32_t sbase = (uint32_t)__cvta_generic_to_shared(smem);
    const int tid = threadIdx.x;
    const int lane = tid & 31;
    const int wid = tid >> 5;
    const int wm = (wid & 3) * 32;
    const int wn = (wid >> 2) * 64;
    const int aRow = wm + (lane & 7) + ((lane >> 3) & 1) * 8;
    const int aU = (lane >> 4) & 1;
    const int aX = aRow & 7;
    const int bRow = wn + (lane & 7) + ((lane >> 4) & 1) * 8;
    const int bU = (lane >> 3) & 1;
    const int bX = bRow & 7;
    const int g = lane >> 2;
    const int tig = lane & 3;
    float acc[2][8][4];
#pragma unroll
    for (int mi = 0; mi < 2; mi++)
#pragma unroll
        for (int nj = 0; nj < 8; nj++)
#pragma unroll
            for (int q = 0; q < 4; q++) acc[mi][nj][q] = 0.0f;

    const int colbase = blockIdx.x * 128;
    const int rowBase = blockIdx.y * 256;   // two row-tiles per CTA

    const uint32_t B0 = sbase;
    const uint32_t B1 = sbase + 16384u;
    const uint32_t A0 = sbase + 32768u;
    const uint32_t A1 = sbase + 49152u;

    // prologue: B (resident) + row-tile 0's A
    LOADT16(g_w1hi, g_w1lo, colbase, 0, B0);     // G1
    LOADT16(g_w1hi, g_w1lo, colbase, 1, B1);     // G2
    LOADT16(g_xhi, g_xlo, rowBase, 0, A0);       // G3
    LOADT16(g_xhi, g_xlo, rowBase, 1, A1);       // G4
    asm volatile("cp.async.wait_group 1;");      // B0,B1,A0 ready
    __syncthreads();

    // ---- row-tile 0 ----
    CHUNKP(A0, B0);
    asm volatile("cp.async.wait_group 0;");      // A1 ready
    __syncthreads();                             // A0 free
    LOADT16(g_xhi, g_xlo, rowBase + 128, 0, A0); // G5 (hidden under compute)
    CHUNKP(A1, B1);
    __syncthreads();                             // A1 free
    LOADT16(g_xhi, g_xlo, rowBase + 128, 1, A1); // G6 (hidden under epilogue)
    EPI1(rowBase);

    // ---- row-tile 1 ----
    asm volatile("cp.async.wait_group 1;");      // G5 (A0) ready
    __syncthreads();
    CHUNKP(A0, B0);
    asm volatile("cp.async.wait_group 0;");      // G6 (A1) ready
    __syncthreads();
    CHUNKP(A1, B1);
    __syncthreads();
    EPI1(rowBase + 128);
}

// ===================== PHASE 2 (R15 champion, unchanged) ===================
#define SETUP_N64()                                                          \
    const int tid = threadIdx.x;                                             \
    const int lane = tid & 31;                                               \
    const int wid = tid >> 5;                                                \
    const int wm = (wid & 3) * 32;                                           \
    const int wn = (wid >> 2) * 32;                                          \
    const int aRow = wm + (lane & 7) + ((lane >> 3) & 1) * 8;                \
    const int aU = (lane >> 4) & 1;                                          \
    const int aX = aRow & 7;                                                 \
    const int bRow = wn + (lane & 7) + ((lane >> 4) & 1) * 8;                \
    const int bU = (lane >> 3) & 1;                                          \
    const int bX = bRow & 7;                                                 \
    const int g = lane >> 2;                                                 \
    const int tig = lane & 3;                                                \
    float acc[2][4][4];                                                      \
    _Pragma("unroll")                                                        \
    for (int mi = 0; mi < 2; mi++)                                           \
        _Pragma("unroll")                                                    \
        for (int nj = 0; nj < 4; nj++)                                       \
            _Pragma("unroll")                                                \
            for (int q = 0; q < 4; q++) acc[mi][nj][q] = 0.0f;

#define LOADC64(AH, AL, BH, BL, SSTR, blockRow, colbase, kc, buf)            \
    do {                                                                     \
        const char* ah_ = (const char*)(AH) + (size_t)(blockRow) * (SSTR) +  \
                          (size_t)(kc) * 64;                                 \
        const char* al_ = (const char*)(AL) + (size_t)(blockRow) * (SSTR) +  \
                          (size_t)(kc) * 64;                                 \
        const char* bh_ = (const char*)(BH) + (size_t)(colbase) * (SSTR) +   \
                          (size_t)(kc) * 64;                                 \
        const char* bl_ = (const char*)(BL) + (size_t)(colbase) * (SSTR) +   \
                          (size_t)(kc) * 64;                                 \
        uint32_t ab_ = sbase + (uint32_t)(buf) * 24576u;                     \
        uint32_t bb_ = ab_ + 16384u;                                         \
        _Pragma("unroll")                                                    \
        for (int j_ = 0; j_ < 4; j_++) {                                     \
            int gi_ = tid + 256 * j_;                                        \
            int row_ = gi_ >> 3, u_ = gi_ & 7;                               \
            const char* src_ = ((u_ < 4) ? ah_ : al_) +                      \
                               (size_t)row_ * (SSTR) + (u_ & 3) * 16;        \
            uint32_t dst_ = ab_ + row_ * 128u +                              \
                            (uint32_t)((u_ ^ (row_ & 7)) << 4);              \
            asm volatile("cp.async.cg.shared.global [%0], [%1], 16;"         \
                         :: "r"(dst_), "l"(src_));                           \
        }                                                                    \
        _Pragma("unroll")                                                    \
        for (int j_ = 0; j_ < 2; j_++) {                                     \
            int gi_ = tid + 256 * j_;                                        \
            int row_ = gi_ >> 3, u_ = gi_ & 7;                               \
            const char* src_ = ((u_ < 4) ? bh_ : bl_) +                      \
                               (size_t)row_ * (SSTR) + (u_ & 3) * 16;        \
            uint32_t dst_ = bb_ + row_ * 128u +                              \
                            (uint32_t)((u_ ^ (row_ & 7)) << 4);              \
            asm volatile("cp.async.cg.shared.global [%0], [%1], 16;"         \
                         :: "r"(dst_), "l"(src_));                           \
        }                                                                    \
        asm volatile("cp.async.commit_group;");                              \
    } while (0)

#define CHUNK_MMA64(buf)                                                     \
    do {                                                                     \
        uint32_t ab_ = sbase + (uint32_t)(buf) * 24576u;                     \
        uint32_t bb_ = ab_ + 16384u;                                         \
        _Pragma("unroll")                                                    \
        for (int kk = 0; kk < 2; kk++) {                                     \
            uint32_t a_hi[2][4], a_lo[2][4], b[4][2];                        \
            _Pragma("unroll")                                                \
            for (int mi = 0; mi < 2; mi++) {                                 \
                int row = aRow + mi * 16;                                    \
                uint32_t ad = ab_ + row * 128u +                             \
                              (uint32_t)(((kk * 2 + aU) ^ aX) << 4);         \
                LDSM_X4(a_hi[mi][0], a_hi[mi][1], a_hi[mi][2], a_hi[mi][3],  \
                        ad);                                                 \
            }                                                                \
            _Pragma("unroll")                                                \
            for (int p = 0; p < 2; p++) {                                    \
                int row = bRow + p * 16;                                     \
                uint32_t bd = bb_ + row * 128u +                             \
                              (uint32_t)(((kk * 2 + bU) ^ bX) << 4);         \
                LDSM_X4(b[2 * p][0], b[2 * p][1],                            \
                        b[2 * p + 1][0], b[2 * p + 1][1], bd);               \
            }                                                                \
            _Pragma("unroll")                                                \
            for (int mi = 0; mi < 2; mi++) {                                 \
                int row = aRow + mi * 16;                                    \
                uint32_t ad = ab_ + row * 128u +                             \
                              (uint32_t)(((4 + kk * 2 + aU) ^ aX) << 4);     \
                LDSM_X4(a_lo[mi][0], a_lo[mi][1], a_lo[mi][2], a_lo[mi][3],  \
                        ad);                                                 \
            }                                                                \
            _Pragma("unroll")                                                \
            for (int mi = 0; mi < 2; mi++)                                   \
                _Pragma("unroll")                                            \
                for (int nj = 0; nj < 4; nj++)                               \
                    MMA16816(acc[mi][nj], a_hi[mi], b[nj]);                  \
            _Pragma("unroll")                                                \
            for (int mi = 0; mi < 2; mi++)                                   \
                _Pragma("unroll")                                            \
                for (int nj = 0; nj < 4; nj++)                               \
                    MMA16816(acc[mi][nj], a_lo[mi], b[nj]);                  \
            _Pragma("unroll")                                                \
            for (int p = 0; p < 2; p++) {                                    \
                int row = bRow + p * 16;                                     \
                uint32_t bd = bb_ + row * 128u +                             \
                              (uint32_t)(((4 + kk * 2 + bU) ^ bX) << 4);     \
                LDSM_X4(b[2 * p][0], b[2 * p][1],                            \
                        b[2 * p + 1][0], b[2 * p + 1][1], bd);               \
            }                                                                \
            _Pragma("unroll")                                                \
            for (int mi = 0; mi < 2; mi++)                                   \
                _Pragma("unroll")                                            \
                for (int nj = 0; nj < 4; nj++)                               \
                    MMA16816(acc[mi][nj], a_hi[mi], b[nj]);                  \
        }                                                                    \
    } while (0)

__global__ __launch_bounds__(256, 3)
void mma_phase2_kernel(const float* __restrict__ b2,
                       const float* __restrict__ theta,
                       const float* __restrict__ r_in,
                       const float* __restrict__ eta,
                       float* __restrict__ out) {
    extern __shared__ char smem[];
    const uint32_t sbase = (uint32_t)__cvta_generic_to_shared(smem);
    SETUP_N64();
    const int blockRow = blockIdx.y * 128;
    const int colbase = blockIdx.x * 64;
    constexpr int SSTR = 1024;
    constexpr int NC = 16;

    LOADC64(g_hhi, g_hlo, g_w2hi, g_w2lo, SSTR, blockRow, colbase, 0, 0);
    LOADC64(g_hhi, g_hlo, g_w2hi, g_w2lo, SSTR, blockRow, colbase, 1, 1);
    asm volatile("cp.async.wait_group 1;");
    __syncthreads();

#pragma unroll 1
    for (int c = 0; c < NC; c++) {
        if (c + 2 < NC) {
            int kc = c + 2;
            LOADC64(g_hhi, g_hlo, g_w2hi, g_w2lo, SSTR, blockRow, colbase,
                    kc, kc % 3);
        } else {
            asm volatile("cp.async.commit_group;");
        }
        CHUNK_MMA64(c % 3);
        asm volatile("cp.async.wait_group 1;");
        __syncthreads();
    }

    // ---- Moebius epilogue ----
    const float e = eta[0];
    float bb2[4][2];
#pragma unroll
    for (int nj = 0; nj < 4; nj++) {
        int cc = colbase + wn + nj * 8 + 2 * tig;
        bb2[nj][0] = b2[cc] * e;
        bb2[nj][1] = b2[cc + 1] * e;
    }
    const int d0c = colbase >> 4;           // blockIdx.x * 4
    const int dbloc = wn >> 4;              // 0 or 2
    float* s_out = reinterpret_cast<float*>(smem);   // 128 x 9 floats

#pragma unroll
    for (int mi = 0; mi < 2; mi++)
#pragma unroll
        for (int rsel = 0; rsel < 2; rsel++) {
            int rloc = wm + mi * 16 + g + rsel * 8;
            int grow = blockRow + rloc;
#pragma unroll
            for (int dj = 0; dj < 2; dj++) {
                int dl = dbloc + dj;        // 0..3 within CTA
                int d = d0c + dl;
                float th = theta[grow * DH + d];
                float rr = r_in[grow * DH + d];
                float sn, cs;
                sincosf(th, &sn, &cs);
                float z0 = rr * cs, z1 = rr * sn;
                float rr2 = rr * rr;
                float sumT = 0.0f, sumS = 0.0f;
#pragma unroll
                for (int hf = 0; hf < 2; hf++) {
                    int nj = 2 * dj + hf;
                    float p0 = acc[mi][nj][rsel * 2 + 0] + bb2[nj][0];
                    float p1 = acc[mi][nj][rsel * 2 + 1] + bb2[nj][1];
                    float nrm = sqrtf(p0 * p0 + p1 * p1);
                    float f = rr * 0.99f / (1.0f + nrm);
                    float w0 = f * p0, w1 = f * p1;
                    float zw0 = z0 - w0, zw1 = z1 - w1;
                    float dist2 = zw0 * zw0 + zw1 * zw1;
                    float scale = (rr2 - (w0 * w0 + w1 * w1)) / dist2;
                    float zo0 = scale * zw0 - w0;
                    float zo1 = scale * zw1 - w1;
                    float ang = atan2f(zo1, zo0);
                    if (ang < 0.0f) ang += TWO_PI_F;
                    sumT += ang;
                    sumS += scale;
                }
                sumT += __shfl_xor_sync(0xffffffffu, sumT, 1);
                sumS += __shfl_xor_sync(0xffffffffu, sumS, 1);
                sumT += __shfl_xor_sync(0xffffffffu, sumT, 2);
                sumS += __shfl_xor_sync(0xffffffffu, sumS, 2);
                if (tig == 0) {
                    s_out[rloc * 9 + dl] = sumT * 0.125f;
                    s_out[rloc * 9 + 4 + dl] = logf(sumS * 0.125f + 1e-8f);
                }
            }
        }
    __syncthreads();
#pragma unroll
    for (int it = 0; it < 4; it++) {
        int idx = tid + it * 256;           // 1024 = 128 rows x 2 tensors x 4 d
        int row = idx >> 3;
        int rest = idx & 7;
        int t = rest >> 2;
        int dl = rest & 3;
        float v = s_out[row * 9 + t * 4 + dl];
        out[(size_t)t * B_TOTAL * DH + (size_t)(blockRow + row) * DH +
            d0c + dl] = v;
    }
}

// ---------------- launch ----------------
extern "C" void kernel_launch(void* const* d_in, const int* in_sizes, int n_in,
                              void* d_out, int out_size) {
    const float* theta = (const float*)d_in[0];
    const float* r     = (const float*)d_in[1];
    const float* x     = (const float*)d_in[2];
    const float* W1    = (const float*)d_in[3];
    const float* b1    = (const float*)d_in[4];
    const float* W2    = (const float*)d_in[5];
    const float* b2    = (const float*)d_in[6];
    const float* eta   = (const float*)d_in[7];
    float* out = (float*)d_out;

    pack_all_kernel<<<8192 + 32 + 256, 256>>>(x, W1, W2, eta);

    const int smem1 = 65536 + 34816;     // 100352 B: 4 bufs + hi/lo staging
    const int smem2 = 3 * 24576;         // 73728 B, 3 stages, 3 CTAs/SM
    cudaFuncSetAttribute(mma_phase1_kernel,
                         cudaFuncAttributeMaxDynamicSharedMemorySize, smem1);
    cudaFuncSetAttribute(mma_phase2_kernel,
                         cudaFuncAttributeMaxDynamicSharedMemorySize, smem2);

    dim3 grid1(4, B_TOTAL / 256);        // 2 row-tiles per CTA
    dim3 grid2(8, B_TOTAL / 128);
    mma_phase1_kernel<<<grid1, 256, smem1>>>(b1);
    mma_phase2_kernel<<<grid2, 256, smem2>>>(b2, theta, r, eta, out);
}